// round 14
// baseline (speedup 1.0000x reference)
#include <cuda_runtime.h>
#include <cuda_fp16.h>
#include <cstdint>

// Ordered_GCN: B=64, N=207, K=32, C=8, D_IN=64, D_OUT=64, tokens = 13248.
// R13 = R12 (warp-specialized: 16 scatter warps + 16 MMA warps, mbarrier
// pipeline, no __syncthreads in main loop) + the missing __syncwarp()s:
// a lane-0 mbarrier.arrive only releases lane 0's accesses; __syncwarp first
// makes ALL lanes' smem reads/writes visible before the delegated arrive.
// total = 13248 = 828 * 16 exactly -> no tail guards on the batch path.

#define KNB   32
#define NTHR  1024
#define CHUNK 4
#define TB    16
#define RING  3
#define TOKEN_IN  2048
#define TOKEN_OUT 512

#define WIN_SLOT  32768
#define OFF_A     (RING * WIN_SLOT)            // 98304
#define A_BUF     16384
#define OFF_W     (OFF_A + 2 * A_BUF)          // 131072
#define OFF_IDX   (OFF_W + 65536)              // 196608
#define IDX_SLOT  512
#define OFF_FULL  (OFF_IDX + RING * IDX_SLOT)  // 198144 : full[3]
#define OFF_CONS  (OFF_FULL + 24)              // cons[3]
#define OFF_AF    (OFF_CONS + 24)              // a_full[2]
#define OFF_AE    (OFF_AF + 16)                // a_empty[2]
#define SMEM_BYTES (OFF_AE + 16 + 256)

#define SW128(o) ((o) ^ (((o) >> 3) & 0x70))

__device__ __forceinline__ float fast_tanh(float z) {
    float e = __expf(2.0f * z);
    return 1.0f - __fdividef(2.0f, e + 1.0f);
}

#define MBAR_INIT(addr, cnt) \
    asm volatile("mbarrier.init.shared.b64 [%0], %1;" :: "r"(addr), "r"(cnt) : "memory")
#define MBAR_ARRIVE(addr) \
    asm volatile("mbarrier.arrive.release.cta.shared::cta.b64 _, [%0];" :: "r"(addr) : "memory")
#define MBAR_WAIT(addr, par) do {                                              \
    uint32_t _m = (addr), _p = (par), _d;                                      \
    asm volatile("{\n\t.reg .pred p;\n\t"                                      \
        "mbarrier.try_wait.parity.acquire.cta.shared::cta.b64 p, [%1], %2;\n\t"\
        "selp.b32 %0, 1, 0, p;\n\t}" : "=r"(_d) : "r"(_m), "r"(_p) : "memory");\
    if (!_d) {                                                                 \
        asm volatile("{\n\t.reg .pred P1;\n\t"                                 \
        "WL%=:\n\t"                                                            \
        "mbarrier.try_wait.parity.acquire.cta.shared::cta.b64 P1, [%0], %1, 0x989680;\n\t" \
        "@P1 bra.uni WD%=;\n\t"                                                \
        "bra.uni WL%=;\n\t"                                                    \
        "WD%=:\n\t}" :: "r"(_m), "r"(_p) : "memory");                          \
    }                                                                          \
} while (0)

__global__ void __launch_bounds__(NTHR, 1)
ordered_gcn_kernel(const int* __restrict__ idx,
                   const float* __restrict__ win,
                   const float* __restrict__ W,
                   float* __restrict__ out,
                   int total, int nbatch)
{
    extern __shared__ char raw[];
    char* base = (char*)(((uintptr_t)raw + 127) & ~(uintptr_t)127);
    const uint32_t sb = (uint32_t)__cvta_generic_to_shared(base);
    char* W_s = base + OFF_W;

    const int tid  = threadIdx.x;
    const int lane = tid & 31;
    const int w    = tid >> 5;
    const int grid = gridDim.x;
    const int bid  = blockIdx.x;
    const int nloc = (nbatch - 1 - bid) / grid + 1;   // batches for this CTA

    // ---- issue one 4-token chunk (local batch bb, chunk qq) into slot ----
    auto issue_chunk = [&](int bb, int qq, int slot) {
        if (bb >= nloc) return;
        uint32_t mbar = sb + OFF_FULL + slot * 8;
        size_t cb = (size_t)(bid + bb * grid) * TB + qq * CHUNK;
        asm volatile("mbarrier.arrive.expect_tx.shared.b64 _, [%0], %1;"
                     :: "r"(mbar), "r"(33280u) : "memory");
        asm volatile(
            "cp.async.bulk.shared::cta.global.mbarrier::complete_tx::bytes "
            "[%0], [%1], %2, [%3];"
            :: "r"(sb + slot * WIN_SLOT), "l"((const char*)win + cb * 8192),
               "r"((uint32_t)WIN_SLOT), "r"(mbar) : "memory");
        asm volatile(
            "cp.async.bulk.shared::cta.global.mbarrier::complete_tx::bytes "
            "[%0], [%1], %2, [%3];"
            :: "r"(sb + OFF_IDX + slot * IDX_SLOT), "l"((const char*)idx + cb * 128),
               "r"((uint32_t)IDX_SLOT), "r"(mbar) : "memory");
    };

    if (tid == 0) {
        #pragma unroll
        for (int s = 0; s < RING; s++) {
            MBAR_INIT(sb + OFF_FULL + s * 8, 1);
            MBAR_INIT(sb + OFF_CONS + s * 8, 16);
        }
        MBAR_INIT(sb + OFF_AF + 0, 16); MBAR_INIT(sb + OFF_AF + 8, 16);
        MBAR_INIT(sb + OFF_AE + 0, 16); MBAR_INIT(sb + OFF_AE + 8, 16);
    }

    // ---- convert W fp32 gmem -> fp16 smem (SW128 rows of 128B) ----
    for (int i = tid; i < 16384; i += NTHR) {
        int c = i >> 11, o = (i >> 5) & 63, dp = i & 31;
        float2 v = ((const float2*)W)[i];
        *(__half2*)(W_s + c * 8192 + SW128(o * 128 + dp * 4)) =
            __floats2half2_rn(v.x, v.y);
    }
    __syncthreads();                   // mbars + W_s ready; only block barrier
    if (tid == 0) { issue_chunk(0, 0, 0); issue_chunk(0, 1, 1); issue_chunk(0, 2, 2); }

    if (w < 16) {
        // ================= SCATTER warps (warp0 = producer too) ============
        const int cs = w & 7, js = w >> 3;
        int slot = 0, par = 0;         // parity = (seq/RING)&1, flips on wrap
        for (int bi = 0; bi < nloc; bi++) {
            const int ab = bi & 1;
            if (bi >= 2) MBAR_WAIT(sb + OFF_AE + ab * 8, (uint32_t)(((bi >> 1) - 1) & 1));
            char* Ab = base + OFF_A + ab * A_BUF;
            #pragma unroll
            for (int q = 0; q < 4; q++) {
                MBAR_WAIT(sb + OFF_FULL + slot * 8, (uint32_t)par);
                #pragma unroll
                for (int u = 0; u < 2; u++) {
                    const int jt = js + u * 2;
                    const int* ib = (const int*)(base + OFF_IDX + slot * IDX_SLOT)
                                    + jt * KNB;
                    int my = ib[lane];
                    unsigned mask = __ballot_sync(0xffffffffu, my == cs);
                    int cnt = __popc(mask);
                    float rc = __fdividef(1.0f, (float)(cnt > 0 ? cnt : 1));
                    const float2* rows =
                        (const float2*)(base + slot * WIN_SLOT + jt * 8192);
                    float s0 = 0.0f, s1 = 0.0f;
                    unsigned m = mask;
                    while (m) {
                        int k = __ffs(m) - 1;
                        m &= m - 1;
                        float2 v = rows[k * 32 + lane];
                        s0 += v.x; s1 += v.y;
                    }
                    int row = cs * 16 + q * 4 + jt;
                    *(__half2*)(Ab + SW128(row * 128 + lane * 4)) =
                        __floats2half2_rn(s0 * rc, s1 * rc);
                }
                __syncwarp();          // ALL lanes' slot reads done -> visible
                if (lane == 0) {
                    MBAR_ARRIVE(sb + OFF_CONS + slot * 8);
                    if (w == 0) {      // producer: refill as soon as drained
                        int seq = bi * 4 + q + 3;       // 3 ahead, same slot
                        if (seq < nloc * 4) {
                            MBAR_WAIT(sb + OFF_CONS + slot * 8, (uint32_t)par);
                            issue_chunk(seq >> 2, seq & 3, slot);
                        }
                    }
                }
                if (++slot == RING) { slot = 0; par ^= 1; }
            }
            __syncwarp();              // ALL lanes' A stores visible
            if (lane == 0) MBAR_ARRIVE(sb + OFF_AF + ab * 8);
        }
    } else {
        // ================= MMA warps ======================================
        const int mw = w - 16, cm = mw & 7, nh = mw >> 3;
        const uint32_t wbase = sb + OFF_W + cm * 8192;
        for (int bi = 0; bi < nloc; bi++) {
            const int ab = bi & 1;
            MBAR_WAIT(sb + OFF_AF + ab * 8, (uint32_t)((bi >> 1) & 1));
            const uint32_t abase = sb + OFF_A + ab * A_BUF;
            float acc[4][4] = {};
            #pragma unroll
            for (int kk = 0; kk < 4; kk++) {
                uint32_t a0, a1, a2, a3;
                {
                    unsigned row = cm * 16 + (lane & 15);
                    unsigned off = SW128(row * 128 + kk * 32 + ((lane >> 4) << 4));
                    asm volatile(
                        "ldmatrix.sync.aligned.m8n8.x4.shared.b16 {%0,%1,%2,%3}, [%4];"
                        : "=r"(a0), "=r"(a1), "=r"(a2), "=r"(a3) : "r"(abase + off));
                }
                #pragma unroll
                for (int nt = 0; nt < 4; nt++) {
                    uint32_t b0, b1;
                    unsigned nrow = nh * 32 + nt * 8 + (lane & 7);
                    unsigned off  = SW128(nrow * 128 + kk * 32 + ((lane >> 3) & 1) * 16);
                    asm volatile(
                        "ldmatrix.sync.aligned.m8n8.x2.shared.b16 {%0,%1}, [%2];"
                        : "=r"(b0), "=r"(b1) : "r"(wbase + off));
                    asm volatile(
                        "mma.sync.aligned.m16n8k16.row.col.f32.f16.f16.f32 "
                        "{%0,%1,%2,%3}, {%4,%5,%6,%7}, {%8,%9}, {%0,%1,%2,%3};"
                        : "+f"(acc[nt][0]), "+f"(acc[nt][1]),
                          "+f"(acc[nt][2]), "+f"(acc[nt][3])
                        : "r"(a0), "r"(a1), "r"(a2), "r"(a3), "r"(b0), "r"(b1));
                }
            }
            __syncwarp();              // ALL lanes' A (ldmatrix) reads done
            if (lane == 0) MBAR_ARRIVE(sb + OFF_AE + ab * 8);

            // epilogue overlaps next batch's scatter (other warp group)
            const int tb = (bid + bi * grid) * TB;
            #pragma unroll
            for (int nt = 0; nt < 4; nt++) {
                int col = cm * 64 + nh * 32 + nt * 8 + (lane & 3) * 2;
                int r0 = tb + (lane >> 2), r1 = r0 + 8;
                float2 v0 = { fast_tanh(acc[nt][0]), fast_tanh(acc[nt][1]) };
                float2 v1 = { fast_tanh(acc[nt][2]), fast_tanh(acc[nt][3]) };
                __stcs((float2*)(out + (size_t)r0 * TOKEN_OUT + col), v0);
                __stcs((float2*)(out + (size_t)r1 * TOKEN_OUT + col), v1);
            }
        }
    }
}

extern "C" void kernel_launch(void* const* d_in, const int* in_sizes, int n_in,
                              void* d_out, int out_size) {
    const int*   idx = (const int*)d_in[0];   // [B,N,K] int32
    const float* win = (const float*)d_in[1]; // [B,N,K,D_IN] f32
    const float* W   = (const float*)d_in[2]; // [C,D_OUT,D_IN] f32
    float* out = (float*)d_out;               // [B,N,C,D_OUT] f32

    const int total  = in_sizes[0] / KNB;     // 13248
    const int nbatch = total / TB;            // 828 (exact)

    static int smem_set = 0;
    if (!smem_set) {
        cudaFuncSetAttribute(ordered_gcn_kernel,
                             cudaFuncAttributeMaxDynamicSharedMemorySize,
                             SMEM_BYTES);
        smem_set = 1;
    }

    int sms = 148, dev = 0;
    cudaGetDevice(&dev);
    cudaDeviceGetAttribute(&sms, cudaDevAttrMultiProcessorCount, dev);
    int grid = (sms < nbatch) ? sms : nbatch;

    ordered_gcn_kernel<<<grid, NTHR, SMEM_BYTES>>>(idx, win, W, out, total, nbatch);
}

// round 16
// speedup vs baseline: 1.5838x; 1.5838x over previous
#include <cuda_runtime.h>
#include <cuda_fp16.h>
#include <cstdint>

// Ordered_GCN: B=64, N=207, K=32, C=8, D_IN=64, D_OUT=64, tokens = 13248.
// R14 = R10 (best: 39.7us; HMMA GEMM, per-chunk barrier pipeline) with:
//  (1) W pre-converted by an init kernel into mma.m16n8k16 B-fragment layout
//      in a __device__ table; MMA warps __ldg their 16 frag words per batch.
//      -> no W in smem, no B-side ldmatrix. Identical numerics.
//  (2) freed 64KB -> RING=6 input slots, issue depth 5 (160KB in flight).
// total = 13248 = 828 * 16 exactly -> no tail guards on the batch path.

#define KNB   32
#define NTHR  1024
#define CHUNK 4
#define TB    16
#define RING  6
#define DEPTH 5
#define TOKEN_IN  2048
#define TOKEN_OUT 512

#define WIN_SLOT  32768                         // 4 tokens * 8KB
#define OFF_A     (RING * WIN_SLOT)             // 196608
#define A_BUF     16384                         // 128 rows x 128B
#define OFF_IDX   (OFF_A + A_BUF)               // 212992
#define IDX_SLOT  512
#define OFF_MBAR  (OFF_IDX + RING * IDX_SLOT)   // 216064
#define SMEM_BYTES (OFF_MBAR + 64 + 1024)       // ~212KB

#define SW128(o) ((o) ^ (((o) >> 3) & 0x70))

// B-fragment table: [c][nq][kk][nt][reg][lane] as half2 -> 16384 entries, 64KB
__device__ __half2 g_wfrag[16384];

__global__ void wconv_kernel(const float* __restrict__ W) {
    int i = blockIdx.x * blockDim.x + threadIdx.x;   // 0..16383
    int lane = i & 31;
    int reg  = (i >> 5) & 1;
    int nt   = (i >> 6) & 1;
    int kk   = (i >> 7) & 3;
    int nq   = (i >> 9) & 3;
    int c    = (i >> 11) & 7;
    int n = nq * 16 + nt * 8 + (lane >> 2);
    int k = kk * 16 + 2 * (lane & 3) + reg * 8;
    const float* row = W + ((c * 64 + n) * 64 + k);
    g_wfrag[i] = __floats2half2_rn(row[0], row[1]);
}

__device__ __forceinline__ float fast_tanh(float z) {
    float e = __expf(2.0f * z);
    return 1.0f - __fdividef(2.0f, e + 1.0f);
}

#define MBAR_INIT(addr, cnt) \
    asm volatile("mbarrier.init.shared.b64 [%0], %1;" :: "r"(addr), "r"(cnt) : "memory")
#define MBAR_WAIT(addr, par) do {                                              \
    uint32_t _m = (addr), _p = (par), _d;                                      \
    asm volatile("{\n\t.reg .pred p;\n\t"                                      \
        "mbarrier.try_wait.parity.acquire.cta.shared::cta.b64 p, [%1], %2;\n\t"\
        "selp.b32 %0, 1, 0, p;\n\t}" : "=r"(_d) : "r"(_m), "r"(_p) : "memory");\
    if (!_d) {                                                                 \
        asm volatile("{\n\t.reg .pred P1;\n\t"                                 \
        "WL%=:\n\t"                                                            \
        "mbarrier.try_wait.parity.acquire.cta.shared::cta.b64 P1, [%0], %1, 0x989680;\n\t" \
        "@P1 bra.uni WD%=;\n\t"                                                \
        "bra.uni WL%=;\n\t"                                                    \
        "WD%=:\n\t}" :: "r"(_m), "r"(_p) : "memory");                          \
    }                                                                          \
} while (0)

__global__ void __launch_bounds__(NTHR, 1)
ordered_gcn_kernel(const int* __restrict__ idx,
                   const float* __restrict__ win,
                   float* __restrict__ out,
                   int total, int nbatch)
{
    extern __shared__ char raw[];
    char* base = (char*)(((uintptr_t)raw + 1023) & ~(uintptr_t)1023);
    const uint32_t sb = (uint32_t)__cvta_generic_to_shared(base);

    const int tid  = threadIdx.x;
    const int lane = tid & 31;
    const int w    = tid >> 5;
    const int grid = gridDim.x;

    // ---- one-thread bulk staging of a 4-token chunk into ring slot ----
    auto issue_chunk = [&](int seq, int slot) {
        int bb = blockIdx.x + (seq >> 2) * grid;
        if (bb >= nbatch) return;
        uint32_t mbar = sb + OFF_MBAR + slot * 8;
        size_t cb = (size_t)bb * TB + (seq & 3) * CHUNK;
        asm volatile("mbarrier.arrive.expect_tx.shared.b64 _, [%0], %1;"
                     :: "r"(mbar), "r"(33280u) : "memory");
        asm volatile(
            "cp.async.bulk.shared::cta.global.mbarrier::complete_tx::bytes "
            "[%0], [%1], %2, [%3];"
            :: "r"(sb + slot * WIN_SLOT), "l"((const char*)win + cb * 8192),
               "r"((uint32_t)WIN_SLOT), "r"(mbar) : "memory");
        asm volatile(
            "cp.async.bulk.shared::cta.global.mbarrier::complete_tx::bytes "
            "[%0], [%1], %2, [%3];"
            :: "r"(sb + OFF_IDX + slot * IDX_SLOT), "l"((const char*)idx + cb * 128),
               "r"((uint32_t)IDX_SLOT), "r"(mbar) : "memory");
    };

    if (tid == 0) {
        #pragma unroll
        for (int s = 0; s < RING; s++) MBAR_INIT(sb + OFF_MBAR + s * 8, 1);
    }
    __syncthreads();                 // mbar init visible before any wait/issue
    if (tid == 0) {
        #pragma unroll
        for (int s = 0; s < DEPTH; s++) issue_chunk(s, s);
    }

    // roles (both decompose the 32 warps the same way)
    const int cs = w & 7, js = w >> 3;   // scatter: class cs, token js in chunk
    const int cm = w & 7, nq = w >> 3;   // mma: class cm, n-quarter nq

    char* A_s = base + OFF_A;
    const uint32_t abase = sb + OFF_A;
    const __half2* wf = g_wfrag + (cm * 2048 + nq * 512);   // (c,nq) block

    int slot = 0, par = 0;               // consumer ring cursor
    int bi = 0;
    for (int b = blockIdx.x; b < nbatch; b += grid, ++bi) {
        // ---- 4 chunks: scatter class-means into A ----
        #pragma unroll
        for (int q = 0; q < 4; q++) {
            const int seq = bi * 4 + q;
            MBAR_WAIT(sb + OFF_MBAR + slot * 8, (uint32_t)par);
            __syncthreads();   // all readers of slot consumed last round done;
                               // (q==0) all prior-batch A reads complete

            const int* ib = (const int*)(base + OFF_IDX + slot * IDX_SLOT) + js * KNB;
            int my = ib[lane];
            unsigned mask = __ballot_sync(0xffffffffu, my == cs);
            int cnt = __popc(mask);
            float rc = __fdividef(1.0f, (float)(cnt > 0 ? cnt : 1));
            const float2* rows = (const float2*)(base + slot * WIN_SLOT + js * 8192);
            float s0 = 0.0f, s1 = 0.0f;
            unsigned m = mask;
            while (m) {
                int k = __ffs(m) - 1;
                m &= m - 1;
                float2 v = rows[k * 32 + lane];
                s0 += v.x; s1 += v.y;
            }
            int row = cs * 16 + q * CHUNK + js;      // [class][token-in-batch]
            *(__half2*)(A_s + SW128(row * 128 + lane * 4)) =
                __floats2half2_rn(s0 * rc, s1 * rc);

            if (tid == 0) {
                // refill the slot consumed one chunk ago (barrier-protected)
                int rslot = slot - 1; if (rslot < 0) rslot = RING - 1;
                issue_chunk(seq + DEPTH, rslot);
            }
            if (++slot == RING) { slot = 0; par ^= 1; }
        }
        __syncthreads();                 // A complete

        // ---- MMA: M=16 tokens, N=16 (quarter), K=64, 4 k-steps ----
        float acc[2][4] = {};
        #pragma unroll
        for (int kk = 0; kk < 4; kk++) {
            uint32_t a0, a1, a2, a3;
            {
                unsigned row = cm * 16 + (lane & 15);
                unsigned off = SW128(row * 128 + kk * 32 + ((lane >> 4) << 4));
                asm volatile(
                    "ldmatrix.sync.aligned.m8n8.x4.shared.b16 {%0,%1,%2,%3}, [%4];"
                    : "=r"(a0), "=r"(a1), "=r"(a2), "=r"(a3) : "r"(abase + off));
            }
            #pragma unroll
            for (int nt = 0; nt < 2; nt++) {
                const __half2* fp = wf + (kk * 128 + nt * 64) + lane;
                uint32_t b0 = *(const uint32_t*)__builtin_assume_aligned(fp, 4);
                uint32_t b1 = *(const uint32_t*)__builtin_assume_aligned(fp + 32, 4);
                asm volatile(
                    "mma.sync.aligned.m16n8k16.row.col.f32.f16.f16.f32 "
                    "{%0,%1,%2,%3}, {%4,%5,%6,%7}, {%8,%9}, {%0,%1,%2,%3};"
                    : "+f"(acc[nt][0]), "+f"(acc[nt][1]),
                      "+f"(acc[nt][2]), "+f"(acc[nt][3])
                    : "r"(a0), "r"(a1), "r"(a2), "r"(a3), "r"(b0), "r"(b1));
            }
        }
        __syncthreads();                 // A reads done -> next batch may write

        // ---- epilogue: tanh + store ----
        const int tb = b * TB;
        #pragma unroll
        for (int nt = 0; nt < 2; nt++) {
            int col = cm * 64 + nq * 16 + nt * 8 + (lane & 3) * 2;
            int r0 = tb + (lane >> 2), r1 = r0 + 8;
            float2 v0 = { fast_tanh(acc[nt][0]), fast_tanh(acc[nt][1]) };
            float2 v1 = { fast_tanh(acc[nt][2]), fast_tanh(acc[nt][3]) };
            *(float2*)(out + (size_t)r0 * TOKEN_OUT + col) = v0;
            *(float2*)(out + (size_t)r1 * TOKEN_OUT + col) = v1;
        }
    }
}

extern "C" void kernel_launch(void* const* d_in, const int* in_sizes, int n_in,
                              void* d_out, int out_size) {
    const int*   idx = (const int*)d_in[0];   // [B,N,K] int32
    const float* win = (const float*)d_in[1]; // [B,N,K,D_IN] f32
    const float* W   = (const float*)d_in[2]; // [C,D_OUT,D_IN] f32
    float* out = (float*)d_out;               // [B,N,C,D_OUT] f32

    const int total  = in_sizes[0] / KNB;     // 13248
    const int nbatch = total / TB;            // 828 (exact)

    static int smem_set = 0;
    if (!smem_set) {
        cudaFuncSetAttribute(ordered_gcn_kernel,
                             cudaFuncAttributeMaxDynamicSharedMemorySize,
                             SMEM_BYTES);
        smem_set = 1;
    }

    int sms = 148, dev = 0;
    cudaGetDevice(&dev);
    cudaDeviceGetAttribute(&sms, cudaDevAttrMultiProcessorCount, dev);
    int grid = (sms < nbatch) ? sms : nbatch;

    wconv_kernel<<<16, 1024>>>(W);            // B-fragment table (64KB)
    ordered_gcn_kernel<<<grid, NTHR, SMEM_BYTES>>>(idx, win, out, total, nbatch);
}